// round 15
// baseline (speedup 1.0000x reference)
#include <cuda_runtime.h>
#include <math.h>

#define BB 4
#define SS 2048
#define DD 1024
#define HH 16
#define HD 64
#define MM (BB*SS)   // 8192

// ---------------- scratch (device globals; no allocation allowed) ----------------
__device__ float g_Q[(size_t)MM*DD];    // [B,H,S,HD], pre-scaled by 1/8
__device__ float g_K[(size_t)MM*DD];    // [B,H,S,HD]
__device__ float g_V[(size_t)MM*DD];    // [B,H,S,HD]
__device__ float g_ctx[(size_t)MM*DD];  // [B,S,D]
__device__ float g_xn[(size_t)MM*DD];   // [B,S,D] layernormed

// ---------------- SGEMM config ----------------
#define Bb_M 128
#define Bb_N 128
#define Bb_K 16
#define PAD 132   // 132*4=528 bytes, 16B aligned rows

// C[m,n] = sum_k A[m,k]*W[n,k]   (both K-major, torch Linear)
// QKV fused via blockIdx.z; epilogue scatters to [B,H,S,HD]
// 2-stage smem double buffering: prefetch slab k0+Bb_K into registers,
// compute on As/Bs[cur], store prefetch into As/Bs[cur^1], sync, swap.
__global__ __launch_bounds__(256) void qkv_gemm_kernel(
    const float* __restrict__ x,
    const float* __restrict__ Wq, const float* __restrict__ bq,
    const float* __restrict__ Wk, const float* __restrict__ bk,
    const float* __restrict__ Wv, const float* __restrict__ bv)
{
    __shared__ float As[2][Bb_K][PAD];
    __shared__ float Bs[2][Bb_K][PAD];

    const float* W; const float* bias; float* out; float scale;
    int z = blockIdx.z;
    if (z == 0)      { W = Wq; bias = bq; out = g_Q; scale = 0.125f; }
    else if (z == 1) { W = Wk; bias = bk; out = g_K; scale = 1.0f;  }
    else             { W = Wv; bias = bv; out = g_V; scale = 1.0f;  }

    int n0 = blockIdx.x * Bb_N;
    int m0 = blockIdx.y * Bb_M;
    int tid = threadIdx.x;
    int tm = tid >> 4, tn = tid & 15;

    int lr = tid >> 2;          // 0..63
    int lk = (tid & 3) * 4;     // 0,4,8,12

    // prologue: load slab k0=0 into buffer 0
    #pragma unroll
    for (int h = 0; h < 2; h++) {
        int r = lr + 64 * h;
        float4 av = *(const float4*)&x[(size_t)(m0 + r) * DD + lk];
        As[0][lk + 0][r] = av.x; As[0][lk + 1][r] = av.y;
        As[0][lk + 2][r] = av.z; As[0][lk + 3][r] = av.w;
        float4 wv = *(const float4*)&W[(size_t)(n0 + r) * DD + lk];
        Bs[0][lk + 0][r] = wv.x; Bs[0][lk + 1][r] = wv.y;
        Bs[0][lk + 2][r] = wv.z; Bs[0][lk + 3][r] = wv.w;
    }
    __syncthreads();

    float acc[8][8];
    #pragma unroll
    for (int i = 0; i < 8; i++)
        #pragma unroll
        for (int j = 0; j < 8; j++) acc[i][j] = 0.0f;

    int cur = 0;
    for (int k0 = 0; k0 < DD; k0 += Bb_K) {
        int nxt = cur ^ 1;
        bool pre = (k0 + Bb_K) < DD;
        float4 pav[2], pwv[2];
        if (pre) {
            #pragma unroll
            for (int h = 0; h < 2; h++) {
                int r = lr + 64 * h;
                pav[h] = *(const float4*)&x[(size_t)(m0 + r) * DD + k0 + Bb_K + lk];
                pwv[h] = *(const float4*)&W[(size_t)(n0 + r) * DD + k0 + Bb_K + lk];
            }
        }
        #pragma unroll
        for (int k = 0; k < Bb_K; k++) {
            float4 a0 = *(const float4*)&As[cur][k][tm * 8];
            float4 a1 = *(const float4*)&As[cur][k][tm * 8 + 4];
            float4 b0 = *(const float4*)&Bs[cur][k][tn * 8];
            float4 b1 = *(const float4*)&Bs[cur][k][tn * 8 + 4];
            float a[8] = {a0.x, a0.y, a0.z, a0.w, a1.x, a1.y, a1.z, a1.w};
            float b[8] = {b0.x, b0.y, b0.z, b0.w, b1.x, b1.y, b1.z, b1.w};
            #pragma unroll
            for (int i = 0; i < 8; i++)
                #pragma unroll
                for (int j = 0; j < 8; j++) acc[i][j] += a[i] * b[j];
        }
        if (pre) {
            #pragma unroll
            for (int h = 0; h < 2; h++) {
                int r = lr + 64 * h;
                As[nxt][lk + 0][r] = pav[h].x; As[nxt][lk + 1][r] = pav[h].y;
                As[nxt][lk + 2][r] = pav[h].z; As[nxt][lk + 3][r] = pav[h].w;
                Bs[nxt][lk + 0][r] = pwv[h].x; Bs[nxt][lk + 1][r] = pwv[h].y;
                Bs[nxt][lk + 2][r] = pwv[h].z; Bs[nxt][lk + 3][r] = pwv[h].w;
            }
        }
        __syncthreads();
        cur = nxt;
    }

    #pragma unroll
    for (int i = 0; i < 8; i++) {
        int m = m0 + tm * 8 + i;
        int b = m >> 11;       // / 2048
        int s = m & 2047;
        #pragma unroll
        for (int j = 0; j < 8; j++) {
            int n = n0 + tn * 8 + j;
            int hh = n >> 6;
            int hd = n & 63;
            float v = (acc[i][j] + bias[n]) * scale;
            out[(((size_t)(b * HH + hh)) * SS + s) * HD + hd] = v;
        }
    }
}

// Output projection: y = leaky(xn @ Wo^T + bo) * mask   (same double buffering)
__global__ __launch_bounds__(256) void out_gemm_kernel(
    const float* __restrict__ Wo, const float* __restrict__ bo,
    const float* __restrict__ mask, float* __restrict__ out)
{
    __shared__ float As[2][Bb_K][PAD];
    __shared__ float Bs[2][Bb_K][PAD];

    int n0 = blockIdx.x * Bb_N;
    int m0 = blockIdx.y * Bb_M;
    int tid = threadIdx.x;
    int tm = tid >> 4, tn = tid & 15;

    int lr = tid >> 2;
    int lk = (tid & 3) * 4;

    #pragma unroll
    for (int h = 0; h < 2; h++) {
        int r = lr + 64 * h;
        float4 av = *(const float4*)&g_xn[(size_t)(m0 + r) * DD + lk];
        As[0][lk + 0][r] = av.x; As[0][lk + 1][r] = av.y;
        As[0][lk + 2][r] = av.z; As[0][lk + 3][r] = av.w;
        float4 wv = *(const float4*)&Wo[(size_t)(n0 + r) * DD + lk];
        Bs[0][lk + 0][r] = wv.x; Bs[0][lk + 1][r] = wv.y;
        Bs[0][lk + 2][r] = wv.z; Bs[0][lk + 3][r] = wv.w;
    }
    __syncthreads();

    float acc[8][8];
    #pragma unroll
    for (int i = 0; i < 8; i++)
        #pragma unroll
        for (int j = 0; j < 8; j++) acc[i][j] = 0.0f;

    int cur = 0;
    for (int k0 = 0; k0 < DD; k0 += Bb_K) {
        int nxt = cur ^ 1;
        bool pre = (k0 + Bb_K) < DD;
        float4 pav[2], pwv[2];
        if (pre) {
            #pragma unroll
            for (int h = 0; h < 2; h++) {
                int r = lr + 64 * h;
                pav[h] = *(const float4*)&g_xn[(size_t)(m0 + r) * DD + k0 + Bb_K + lk];
                pwv[h] = *(const float4*)&Wo[(size_t)(n0 + r) * DD + k0 + Bb_K + lk];
            }
        }
        #pragma unroll
        for (int k = 0; k < Bb_K; k++) {
            float4 a0 = *(const float4*)&As[cur][k][tm * 8];
            float4 a1 = *(const float4*)&As[cur][k][tm * 8 + 4];
            float4 b0 = *(const float4*)&Bs[cur][k][tn * 8];
            float4 b1 = *(const float4*)&Bs[cur][k][tn * 8 + 4];
            float a[8] = {a0.x, a0.y, a0.z, a0.w, a1.x, a1.y, a1.z, a1.w};
            float b[8] = {b0.x, b0.y, b0.z, b0.w, b1.x, b1.y, b1.z, b1.w};
            #pragma unroll
            for (int i = 0; i < 8; i++)
                #pragma unroll
                for (int j = 0; j < 8; j++) acc[i][j] += a[i] * b[j];
        }
        if (pre) {
            #pragma unroll
            for (int h = 0; h < 2; h++) {
                int r = lr + 64 * h;
                As[nxt][lk + 0][r] = pav[h].x; As[nxt][lk + 1][r] = pav[h].y;
                As[nxt][lk + 2][r] = pav[h].z; As[nxt][lk + 3][r] = pav[h].w;
                Bs[nxt][lk + 0][r] = pwv[h].x; Bs[nxt][lk + 1][r] = pwv[h].y;
                Bs[nxt][lk + 2][r] = pwv[h].z; Bs[nxt][lk + 3][r] = pwv[h].w;
            }
        }
        __syncthreads();
        cur = nxt;
    }

    #pragma unroll
    for (int i = 0; i < 8; i++) {
        int m = m0 + tm * 8 + i;
        float mk = mask[m];
        #pragma unroll
        for (int j = 0; j < 8; j++) {
            int n = n0 + tn * 8 + j;
            float y = acc[i][j] + bo[n];
            y = (y >= 0.0f) ? y : 0.01f * y;
            out[(size_t)m * DD + n] = y * mk;
        }
    }
}

// ---------------- flash attention (fp32, online softmax) ----------------
#define APAD 68   // 68*4=272 bytes, 16B aligned rows

__global__ __launch_bounds__(256) void attn_kernel(const float* __restrict__ mask)
{
    extern __shared__ float sm[];
    float* Qts = sm;                   // [d][r]  64 x APAD
    float* Kts = Qts + 64 * APAD;      // [d][c]
    float* Vs  = Kts + 64 * APAD;      // [k][d]
    float* Ps  = Vs  + 64 * APAD;      // [r][k]
    float* am  = Ps  + 64 * APAD;      // [64]

    int qt = blockIdx.x;   // 0..31 query tiles
    int bh = blockIdx.y;   // 0..63
    int b = bh >> 4;
    int h = bh & 15;
    const float* Qg = g_Q + (size_t)bh * SS * HD + (size_t)qt * 64 * HD;
    const float* Kg = g_K + (size_t)bh * SS * HD;
    const float* Vg = g_V + (size_t)bh * SS * HD;

    int tid = threadIdx.x;
    int ty = tid >> 4, tx = tid & 15;

    // load Q tile transposed: Qts[d][r]
    for (int t = tid; t < 64 * 16; t += 256) {
        int r = t >> 4; int c4 = (t & 15) * 4;
        float4 v = *(const float4*)&Qg[r * HD + c4];
        Qts[(c4 + 0) * APAD + r] = v.x;
        Qts[(c4 + 1) * APAD + r] = v.y;
        Qts[(c4 + 2) * APAD + r] = v.z;
        Qts[(c4 + 3) * APAD + r] = v.w;
    }

    float o[4][4];
    float mrow[4], lrow[4];
    #pragma unroll
    for (int i = 0; i < 4; i++) {
        mrow[i] = -1e30f; lrow[i] = 0.0f;
        #pragma unroll
        for (int j = 0; j < 4; j++) o[i][j] = 0.0f;
    }

    for (int jt = 0; jt < SS / 64; jt++) {
        __syncthreads();   // Ps/V consumed from previous iter; Q load done (iter 0)
        const float* Kgj = Kg + (size_t)jt * 64 * HD;
        const float* Vgj = Vg + (size_t)jt * 64 * HD;
        for (int t = tid; t < 64 * 16; t += 256) {
            int r = t >> 4; int c4 = (t & 15) * 4;
            float4 kv = *(const float4*)&Kgj[r * HD + c4];
            Kts[(c4 + 0) * APAD + r] = kv.x;
            Kts[(c4 + 1) * APAD + r] = kv.y;
            Kts[(c4 + 2) * APAD + r] = kv.z;
            Kts[(c4 + 3) * APAD + r] = kv.w;
            float4 vv = *(const float4*)&Vgj[r * HD + c4];
            *(float4*)&Vs[r * APAD + c4] = vv;
        }
        if (tid < 64) am[tid] = (1.0f - mask[b * SS + jt * 64 + tid]) * -10000.0f;
        __syncthreads();

        // scores s[4][4] = Q . K^T  (Q already scaled by 1/sqrt(HD))
        float s[4][4];
        #pragma unroll
        for (int i = 0; i < 4; i++)
            #pragma unroll
            for (int j = 0; j < 4; j++) s[i][j] = 0.0f;
        #pragma unroll 8
        for (int d = 0; d < HD; d++) {
            float4 aq = *(const float4*)&Qts[d * APAD + ty * 4];
            float4 bk4 = *(const float4*)&Kts[d * APAD + tx * 4];
            float a[4] = {aq.x, aq.y, aq.z, aq.w};
            float bb[4] = {bk4.x, bk4.y, bk4.z, bk4.w};
            #pragma unroll
            for (int i = 0; i < 4; i++)
                #pragma unroll
                for (int j = 0; j < 4; j++) s[i][j] += a[i] * bb[j];
        }
        #pragma unroll
        for (int i = 0; i < 4; i++)
            #pragma unroll
            for (int j = 0; j < 4; j++) s[i][j] += am[tx * 4 + j];

        // online softmax per row
        #pragma unroll
        for (int i = 0; i < 4; i++) {
            float mt = fmaxf(fmaxf(s[i][0], s[i][1]), fmaxf(s[i][2], s[i][3]));
            #pragma unroll
            for (int off = 8; off; off >>= 1)
                mt = fmaxf(mt, __shfl_xor_sync(0xffffffffu, mt, off, 16));
            float mnew = fmaxf(mrow[i], mt);
            float corr = __expf(mrow[i] - mnew);
            mrow[i] = mnew;
            float ls = 0.0f;
            #pragma unroll
            for (int j = 0; j < 4; j++) {
                float p = __expf(s[i][j] - mnew);
                Ps[(ty * 4 + i) * APAD + tx * 4 + j] = p;
                ls += p;
            }
            #pragma unroll
            for (int off = 8; off; off >>= 1)
                ls += __shfl_xor_sync(0xffffffffu, ls, off, 16);
            lrow[i] = lrow[i] * corr + ls;
            #pragma unroll
            for (int j = 0; j < 4; j++) o[i][j] *= corr;
        }
        __syncthreads();

        // O += P . V
        #pragma unroll 8
        for (int k = 0; k < 64; k++) {
            float4 vv = *(const float4*)&Vs[k * APAD + tx * 4];
            float p[4];
            #pragma unroll
            for (int i = 0; i < 4; i++) p[i] = Ps[(ty * 4 + i) * APAD + k];
            #pragma unroll
            for (int i = 0; i < 4; i++) {
                o[i][0] += p[i] * vv.x;
                o[i][1] += p[i] * vv.y;
                o[i][2] += p[i] * vv.z;
                o[i][3] += p[i] * vv.w;
            }
        }
    }

    // write ctx [B,S,D]
    #pragma unroll
    for (int i = 0; i < 4; i++) {
        float inv = 1.0f / lrow[i];
        int sg = qt * 64 + ty * 4 + i;
        float4 w;
        w.x = o[i][0] * inv; w.y = o[i][1] * inv;
        w.z = o[i][2] * inv; w.w = o[i][3] * inv;
        *(float4*)&g_ctx[((size_t)(b * SS + sg)) * DD + h * HD + tx * 4] = w;
    }
}

// ---------------- residual + layernorm ----------------
__global__ __launch_bounds__(256) void ln_kernel(
    const float* __restrict__ resid,
    const float* __restrict__ gam, const float* __restrict__ bet)
{
    int row = blockIdx.x;
    int tid = threadIdx.x;
    const float* cp = g_ctx + (size_t)row * DD;
    const float* rp = resid + (size_t)row * DD;
    float4 a = *(const float4*)&cp[tid * 4];
    float4 r = *(const float4*)&rp[tid * 4];
    float v[4] = {a.x + r.x, a.y + r.y, a.z + r.z, a.w + r.w};
    float sum = v[0] + v[1] + v[2] + v[3];
    float sq  = v[0]*v[0] + v[1]*v[1] + v[2]*v[2] + v[3]*v[3];
    #pragma unroll
    for (int off = 16; off; off >>= 1) {
        sum += __shfl_xor_sync(0xffffffffu, sum, off);
        sq  += __shfl_xor_sync(0xffffffffu, sq,  off);
    }
    __shared__ float s1[8], s2[8];
    if ((tid & 31) == 0) { s1[tid >> 5] = sum; s2[tid >> 5] = sq; }
    __syncthreads();
    if (tid == 0) {
        float ts = 0.0f, tq = 0.0f;
        #pragma unroll
        for (int i = 0; i < 8; i++) { ts += s1[i]; tq += s2[i]; }
        s1[0] = ts; s2[0] = tq;
    }
    __syncthreads();
    float mu  = s1[0] * (1.0f / DD);
    float var = s2[0] * (1.0f / DD) - mu * mu;
    float rs  = rsqrtf(var + 1e-5f);
    float4 g4 = *(const float4*)&gam[tid * 4];
    float4 b4 = *(const float4*)&bet[tid * 4];
    float4 o;
    o.x = (v[0] - mu) * rs * g4.x + b4.x;
    o.y = (v[1] - mu) * rs * g4.y + b4.y;
    o.z = (v[2] - mu) * rs * g4.z + b4.z;
    o.w = (v[3] - mu) * rs * g4.w + b4.w;
    *(float4*)&g_xn[(size_t)row * DD + tid * 4] = o;
}

// ---------------- launch ----------------
extern "C" void kernel_launch(void* const* d_in, const int* in_sizes, int n_in,
                              void* d_out, int out_size)
{
    const float* inputs = (const float*)d_in[0];
    const float* mask   = (const float*)d_in[1];
    const float* Wq = (const float*)d_in[2];  const float* bq = (const float*)d_in[3];
    const float* Wk = (const float*)d_in[4];  const float* bk = (const float*)d_in[5];
    const float* Wv = (const float*)d_in[6];  const float* bv = (const float*)d_in[7];
    const float* Wo = (const float*)d_in[8];  const float* bo = (const float*)d_in[9];
    const float* ln_g = (const float*)d_in[10];
    const float* ln_b = (const float*)d_in[11];
    float* out = (float*)d_out;

    dim3 gq(DD / Bb_N, MM / Bb_M, 3);
    qkv_gemm_kernel<<<gq, 256>>>(inputs, Wq, bq, Wk, bk, Wv, bv);

    int smem_attn = (4 * 64 * APAD + 64) * (int)sizeof(float);
    cudaFuncSetAttribute(attn_kernel, cudaFuncAttributeMaxDynamicSharedMemorySize, smem_attn);
    attn_kernel<<<dim3(SS / 64, BB * HH), 256, smem_attn>>>(mask);

    ln_kernel<<<MM, 256>>>(inputs, ln_g, ln_b);

    out_gemm_kernel<<<dim3(DD / Bb_N, MM / Bb_M), 256>>>(Wo, bo, mask, out);
}

// round 17
// speedup vs baseline: 1.0541x; 1.0541x over previous
#include <cuda_runtime.h>
#include <math.h>

#define BB 4
#define SS 2048
#define DD 1024
#define HH 16
#define HD 64
#define MM (BB*SS)   // 8192

// ---------------- f32x2 packed helpers (B300 double-rate fp32) ----------------
__device__ __forceinline__ void ffma2(unsigned long long &acc, unsigned long long a, unsigned long long b) {
    asm("fma.rn.f32x2 %0, %1, %2, %0;" : "+l"(acc) : "l"(a), "l"(b));
}
__device__ __forceinline__ unsigned long long bcast2(float x) {
    unsigned long long r; unsigned u = __float_as_uint(x);
    asm("mov.b64 %0, {%1, %1};" : "=l"(r) : "r"(u));
    return r;
}
__device__ __forceinline__ void unpack2(unsigned long long v, float &lo, float &hi) {
    unsigned a, b;
    asm("mov.b64 {%0, %1}, %2;" : "=r"(a), "=r"(b) : "l"(v));
    lo = __uint_as_float(a); hi = __uint_as_float(b);
}
__device__ __forceinline__ void mul2(unsigned long long &d, unsigned long long a, unsigned long long b) {
    asm("mul.rn.f32x2 %0, %1, %2;" : "=l"(d) : "l"(a), "l"(b));
}

// ---------------- scratch (device globals; no allocation allowed) ----------------
__device__ float g_Q[(size_t)MM*DD];    // [B,H,S,HD], pre-scaled by 1/8
__device__ float g_K[(size_t)MM*DD];    // [B,H,S,HD]
__device__ float g_V[(size_t)MM*DD];    // [B,H,S,HD]
__device__ float g_ctx[(size_t)MM*DD];  // [B,S,D]
__device__ float g_xn[(size_t)MM*DD];   // [B,S,D] layernormed

// ---------------- SGEMM config ----------------
#define Bb_M 128
#define Bb_N 128
#define Bb_K 16
#define PAD 132   // 132*4=528 bytes, 16B aligned rows

// C[m,n] = sum_k A[m,k]*W[n,k]; 2-stage double buffering + f32x2 packed FMA.
__global__ __launch_bounds__(256) void qkv_gemm_kernel(
    const float* __restrict__ x,
    const float* __restrict__ Wq, const float* __restrict__ bq,
    const float* __restrict__ Wk, const float* __restrict__ bk,
    const float* __restrict__ Wv, const float* __restrict__ bv)
{
    __shared__ float As[2][Bb_K][PAD];
    __shared__ float Bs[2][Bb_K][PAD];

    const float* W; const float* bias; float* out; float scale;
    int z = blockIdx.z;
    if (z == 0)      { W = Wq; bias = bq; out = g_Q; scale = 0.125f; }
    else if (z == 1) { W = Wk; bias = bk; out = g_K; scale = 1.0f;  }
    else             { W = Wv; bias = bv; out = g_V; scale = 1.0f;  }

    int n0 = blockIdx.x * Bb_N;
    int m0 = blockIdx.y * Bb_M;
    int tid = threadIdx.x;
    int tm = tid >> 4, tn = tid & 15;

    int lr = tid >> 2;          // 0..63
    int lk = (tid & 3) * 4;     // 0,4,8,12

    // prologue: load slab k0=0 into buffer 0
    #pragma unroll
    for (int h = 0; h < 2; h++) {
        int r = lr + 64 * h;
        float4 av = *(const float4*)&x[(size_t)(m0 + r) * DD + lk];
        As[0][lk + 0][r] = av.x; As[0][lk + 1][r] = av.y;
        As[0][lk + 2][r] = av.z; As[0][lk + 3][r] = av.w;
        float4 wv = *(const float4*)&W[(size_t)(n0 + r) * DD + lk];
        Bs[0][lk + 0][r] = wv.x; Bs[0][lk + 1][r] = wv.y;
        Bs[0][lk + 2][r] = wv.z; Bs[0][lk + 3][r] = wv.w;
    }
    __syncthreads();

    unsigned long long acc2[8][4];
    #pragma unroll
    for (int i = 0; i < 8; i++)
        #pragma unroll
        for (int j = 0; j < 4; j++) acc2[i][j] = 0ULL;

    int cur = 0;
    for (int k0 = 0; k0 < DD; k0 += Bb_K) {
        int nxt = cur ^ 1;
        bool pre = (k0 + Bb_K) < DD;
        float4 pav[2], pwv[2];
        if (pre) {
            #pragma unroll
            for (int h = 0; h < 2; h++) {
                int r = lr + 64 * h;
                pav[h] = *(const float4*)&x[(size_t)(m0 + r) * DD + k0 + Bb_K + lk];
                pwv[h] = *(const float4*)&W[(size_t)(n0 + r) * DD + k0 + Bb_K + lk];
            }
        }
        #pragma unroll
        for (int k = 0; k < Bb_K; k++) {
            float4 a0 = *(const float4*)&As[cur][k][tm * 8];
            float4 a1 = *(const float4*)&As[cur][k][tm * 8 + 4];
            ulonglong2 bq0 = *(const ulonglong2*)&Bs[cur][k][tn * 8];
            ulonglong2 bq1 = *(const ulonglong2*)&Bs[cur][k][tn * 8 + 4];
            unsigned long long av[8] = {
                bcast2(a0.x), bcast2(a0.y), bcast2(a0.z), bcast2(a0.w),
                bcast2(a1.x), bcast2(a1.y), bcast2(a1.z), bcast2(a1.w)};
            unsigned long long bv[4] = {bq0.x, bq0.y, bq1.x, bq1.y};
            #pragma unroll
            for (int i = 0; i < 8; i++)
                #pragma unroll
                for (int j = 0; j < 4; j++) ffma2(acc2[i][j], av[i], bv[j]);
        }
        if (pre) {
            #pragma unroll
            for (int h = 0; h < 2; h++) {
                int r = lr + 64 * h;
                As[nxt][lk + 0][r] = pav[h].x; As[nxt][lk + 1][r] = pav[h].y;
                As[nxt][lk + 2][r] = pav[h].z; As[nxt][lk + 3][r] = pav[h].w;
                Bs[nxt][lk + 0][r] = pwv[h].x; Bs[nxt][lk + 1][r] = pwv[h].y;
                Bs[nxt][lk + 2][r] = pwv[h].z; Bs[nxt][lk + 3][r] = pwv[h].w;
            }
        }
        __syncthreads();
        cur = nxt;
    }

    #pragma unroll
    for (int i = 0; i < 8; i++) {
        int m = m0 + tm * 8 + i;
        int b = m >> 11;       // / 2048
        int s = m & 2047;
        float c[8];
        #pragma unroll
        for (int j = 0; j < 4; j++) unpack2(acc2[i][j], c[2*j], c[2*j+1]);
        #pragma unroll
        for (int j = 0; j < 8; j++) {
            int n = n0 + tn * 8 + j;
            int hh = n >> 6;
            int hd = n & 63;
            float v = (c[j] + bias[n]) * scale;
            out[(((size_t)(b * HH + hh)) * SS + s) * HD + hd] = v;
        }
    }
}

// Output projection: y = leaky(xn @ Wo^T + bo) * mask   (double buffering + f32x2)
__global__ __launch_bounds__(256) void out_gemm_kernel(
    const float* __restrict__ Wo, const float* __restrict__ bo,
    const float* __restrict__ mask, float* __restrict__ out)
{
    __shared__ float As[2][Bb_K][PAD];
    __shared__ float Bs[2][Bb_K][PAD];

    int n0 = blockIdx.x * Bb_N;
    int m0 = blockIdx.y * Bb_M;
    int tid = threadIdx.x;
    int tm = tid >> 4, tn = tid & 15;

    int lr = tid >> 2;
    int lk = (tid & 3) * 4;

    #pragma unroll
    for (int h = 0; h < 2; h++) {
        int r = lr + 64 * h;
        float4 av = *(const float4*)&g_xn[(size_t)(m0 + r) * DD + lk];
        As[0][lk + 0][r] = av.x; As[0][lk + 1][r] = av.y;
        As[0][lk + 2][r] = av.z; As[0][lk + 3][r] = av.w;
        float4 wv = *(const float4*)&Wo[(size_t)(n0 + r) * DD + lk];
        Bs[0][lk + 0][r] = wv.x; Bs[0][lk + 1][r] = wv.y;
        Bs[0][lk + 2][r] = wv.z; Bs[0][lk + 3][r] = wv.w;
    }
    __syncthreads();

    unsigned long long acc2[8][4];
    #pragma unroll
    for (int i = 0; i < 8; i++)
        #pragma unroll
        for (int j = 0; j < 4; j++) acc2[i][j] = 0ULL;

    int cur = 0;
    for (int k0 = 0; k0 < DD; k0 += Bb_K) {
        int nxt = cur ^ 1;
        bool pre = (k0 + Bb_K) < DD;
        float4 pav[2], pwv[2];
        if (pre) {
            #pragma unroll
            for (int h = 0; h < 2; h++) {
                int r = lr + 64 * h;
                pav[h] = *(const float4*)&g_xn[(size_t)(m0 + r) * DD + k0 + Bb_K + lk];
                pwv[h] = *(const float4*)&Wo[(size_t)(n0 + r) * DD + k0 + Bb_K + lk];
            }
        }
        #pragma unroll
        for (int k = 0; k < Bb_K; k++) {
            float4 a0 = *(const float4*)&As[cur][k][tm * 8];
            float4 a1 = *(const float4*)&As[cur][k][tm * 8 + 4];
            ulonglong2 bq0 = *(const ulonglong2*)&Bs[cur][k][tn * 8];
            ulonglong2 bq1 = *(const ulonglong2*)&Bs[cur][k][tn * 8 + 4];
            unsigned long long av[8] = {
                bcast2(a0.x), bcast2(a0.y), bcast2(a0.z), bcast2(a0.w),
                bcast2(a1.x), bcast2(a1.y), bcast2(a1.z), bcast2(a1.w)};
            unsigned long long bv[4] = {bq0.x, bq0.y, bq1.x, bq1.y};
            #pragma unroll
            for (int i = 0; i < 8; i++)
                #pragma unroll
                for (int j = 0; j < 4; j++) ffma2(acc2[i][j], av[i], bv[j]);
        }
        if (pre) {
            #pragma unroll
            for (int h = 0; h < 2; h++) {
                int r = lr + 64 * h;
                As[nxt][lk + 0][r] = pav[h].x; As[nxt][lk + 1][r] = pav[h].y;
                As[nxt][lk + 2][r] = pav[h].z; As[nxt][lk + 3][r] = pav[h].w;
                Bs[nxt][lk + 0][r] = pwv[h].x; Bs[nxt][lk + 1][r] = pwv[h].y;
                Bs[nxt][lk + 2][r] = pwv[h].z; Bs[nxt][lk + 3][r] = pwv[h].w;
            }
        }
        __syncthreads();
        cur = nxt;
    }

    #pragma unroll
    for (int i = 0; i < 8; i++) {
        int m = m0 + tm * 8 + i;
        float mk = mask[m];
        float c[8];
        #pragma unroll
        for (int j = 0; j < 4; j++) unpack2(acc2[i][j], c[2*j], c[2*j+1]);
        #pragma unroll
        for (int j = 0; j < 8; j++) {
            int n = n0 + tn * 8 + j;
            float y = c[j] + bo[n];
            y = (y >= 0.0f) ? y : 0.01f * y;
            out[(size_t)m * DD + n] = y * mk;
        }
    }
}

// ---------------- flash attention (fp32, online softmax, f32x2 packed) ----------------
#define APAD 68   // 68*4=272 bytes, 16B aligned rows

__global__ __launch_bounds__(256) void attn_kernel(const float* __restrict__ mask)
{
    extern __shared__ float sm[];
    float* Qts = sm;                   // [d][r]  64 x APAD
    float* Kts = Qts + 64 * APAD;      // [d][c]
    float* Vs  = Kts + 64 * APAD;      // [k][d]
    float* Ps  = Vs  + 64 * APAD;      // [r][k]
    float* am  = Ps  + 64 * APAD;      // [64]

    int qt = blockIdx.x;   // 0..31 query tiles
    int bh = blockIdx.y;   // 0..63
    int b = bh >> 4;
    int h = bh & 15;
    const float* Qg = g_Q + (size_t)bh * SS * HD + (size_t)qt * 64 * HD;
    const float* Kg = g_K + (size_t)bh * SS * HD;
    const float* Vg = g_V + (size_t)bh * SS * HD;

    int tid = threadIdx.x;
    int ty = tid >> 4, tx = tid & 15;

    // load Q tile transposed: Qts[d][r]
    for (int t = tid; t < 64 * 16; t += 256) {
        int r = t >> 4; int c4 = (t & 15) * 4;
        float4 v = *(const float4*)&Qg[r * HD + c4];
        Qts[(c4 + 0) * APAD + r] = v.x;
        Qts[(c4 + 1) * APAD + r] = v.y;
        Qts[(c4 + 2) * APAD + r] = v.z;
        Qts[(c4 + 3) * APAD + r] = v.w;
    }

    unsigned long long o2[4][2];   // packed output accumulators (cols tx*4 .. tx*4+3)
    float mrow[4], lrow[4];
    #pragma unroll
    for (int i = 0; i < 4; i++) {
        mrow[i] = -1e30f; lrow[i] = 0.0f;
        o2[i][0] = 0ULL; o2[i][1] = 0ULL;
    }

    for (int jt = 0; jt < SS / 64; jt++) {
        __syncthreads();   // Ps/V consumed from previous iter; Q load done (iter 0)
        const float* Kgj = Kg + (size_t)jt * 64 * HD;
        const float* Vgj = Vg + (size_t)jt * 64 * HD;
        for (int t = tid; t < 64 * 16; t += 256) {
            int r = t >> 4; int c4 = (t & 15) * 4;
            float4 kv = *(const float4*)&Kgj[r * HD + c4];
            Kts[(c4 + 0) * APAD + r] = kv.x;
            Kts[(c4 + 1) * APAD + r] = kv.y;
            Kts[(c4 + 2) * APAD + r] = kv.z;
            Kts[(c4 + 3) * APAD + r] = kv.w;
            float4 vv = *(const float4*)&Vgj[r * HD + c4];
            *(float4*)&Vs[r * APAD + c4] = vv;
        }
        if (tid < 64) am[tid] = (1.0f - mask[b * SS + jt * 64 + tid]) * -10000.0f;
        __syncthreads();

        // scores: packed s2[i][pair] over keys tx*4..tx*4+3 (Q pre-scaled by 1/8)
        unsigned long long s2[4][2];
        #pragma unroll
        for (int i = 0; i < 4; i++) { s2[i][0] = 0ULL; s2[i][1] = 0ULL; }
        #pragma unroll 8
        for (int d = 0; d < HD; d++) {
            float4 aq = *(const float4*)&Qts[d * APAD + ty * 4];
            ulonglong2 bk2 = *(const ulonglong2*)&Kts[d * APAD + tx * 4];
            unsigned long long aa[4] = {bcast2(aq.x), bcast2(aq.y), bcast2(aq.z), bcast2(aq.w)};
            #pragma unroll
            for (int i = 0; i < 4; i++) {
                ffma2(s2[i][0], aa[i], bk2.x);
                ffma2(s2[i][1], aa[i], bk2.y);
            }
        }
        float s[4][4];
        #pragma unroll
        for (int i = 0; i < 4; i++) {
            unpack2(s2[i][0], s[i][0], s[i][1]);
            unpack2(s2[i][1], s[i][2], s[i][3]);
        }
        #pragma unroll
        for (int i = 0; i < 4; i++)
            #pragma unroll
            for (int j = 0; j < 4; j++) s[i][j] += am[tx * 4 + j];

        // online softmax per row
        #pragma unroll
        for (int i = 0; i < 4; i++) {
            float mt = fmaxf(fmaxf(s[i][0], s[i][1]), fmaxf(s[i][2], s[i][3]));
            #pragma unroll
            for (int off = 8; off; off >>= 1)
                mt = fmaxf(mt, __shfl_xor_sync(0xffffffffu, mt, off, 16));
            float mnew = fmaxf(mrow[i], mt);
            float corr = __expf(mrow[i] - mnew);
            mrow[i] = mnew;
            float ls = 0.0f;
            #pragma unroll
            for (int j = 0; j < 4; j++) {
                float p = __expf(s[i][j] - mnew);
                Ps[(ty * 4 + i) * APAD + tx * 4 + j] = p;
                ls += p;
            }
            #pragma unroll
            for (int off = 8; off; off >>= 1)
                ls += __shfl_xor_sync(0xffffffffu, ls, off, 16);
            lrow[i] = lrow[i] * corr + ls;
            unsigned long long c2 = bcast2(corr);
            mul2(o2[i][0], o2[i][0], c2);
            mul2(o2[i][1], o2[i][1], c2);
        }
        __syncthreads();

        // O += P . V  (packed over the 4 output columns)
        #pragma unroll 8
        for (int k = 0; k < 64; k++) {
            ulonglong2 vv2 = *(const ulonglong2*)&Vs[k * APAD + tx * 4];
            #pragma unroll
            for (int i = 0; i < 4; i++) {
                unsigned long long pp = bcast2(Ps[(ty * 4 + i) * APAD + k]);
                ffma2(o2[i][0], pp, vv2.x);
                ffma2(o2[i][1], pp, vv2.y);
            }
        }
    }

    // write ctx [B,S,D]
    #pragma unroll
    for (int i = 0; i < 4; i++) {
        float inv = 1.0f / lrow[i];
        int sg = qt * 64 + ty * 4 + i;
        float o0, o1, o2f, o3;
        unpack2(o2[i][0], o0, o1);
        unpack2(o2[i][1], o2f, o3);
        float4 w;
        w.x = o0 * inv; w.y = o1 * inv;
        w.z = o2f * inv; w.w = o3 * inv;
        *(float4*)&g_ctx[((size_t)(b * SS + sg)) * DD + h * HD + tx * 4] = w;
    }
}

// ---------------- residual + layernorm ----------------
__global__ __launch_bounds__(256) void ln_kernel(
    const float* __restrict__ resid,
    const float* __restrict__ gam, const float* __restrict__ bet)
{
    int row = blockIdx.x;
    int tid = threadIdx.x;
    const float* cp = g_ctx + (size_t)row * DD;
    const float* rp = resid + (size_t)row * DD;
    float4 a = *(const float4*)&cp[tid * 4];
    float4 r = *(const float4*)&rp[tid * 4];
    float v[4] = {a.x + r.x, a.y + r.y, a.z + r.z, a.w + r.w};
    float sum = v[0] + v[1] + v[2] + v[3];
    float sq  = v[0]*v[0] + v[1]*v[1] + v[2]*v[2] + v[3]*v[3];
    #pragma unroll
    for (int off = 16; off; off >>= 1) {
        sum += __shfl_xor_sync(0xffffffffu, sum, off);
        sq  += __shfl_xor_sync(0xffffffffu, sq,  off);
    }
    __shared__ float s1[8], s2[8];
    if ((tid & 31) == 0) { s1[tid >> 5] = sum; s2[tid >> 5] = sq; }
    __syncthreads();
    if (tid == 0) {
        float ts = 0.0f, tq = 0.0f;
        #pragma unroll
        for (int i = 0; i < 8; i++) { ts += s1[i]; tq += s2[i]; }
        s1[0] = ts; s2[0] = tq;
    }
    __syncthreads();
    float mu  = s1[0] * (1.0f / DD);
    float var = s2[0] * (1.0f / DD) - mu * mu;
    float rs  = rsqrtf(var + 1e-5f);
    float4 g4 = *(const float4*)&gam[tid * 4];
    float4 b4 = *(const float4*)&bet[tid * 4];
    float4 o;
    o.x = (v[0] - mu) * rs * g4.x + b4.x;
    o.y = (v[1] - mu) * rs * g4.y + b4.y;
    o.z = (v[2] - mu) * rs * g4.z + b4.z;
    o.w = (v[3] - mu) * rs * g4.w + b4.w;
    *(float4*)&g_xn[(size_t)row * DD + tid * 4] = o;
}

// ---------------- launch ----------------
extern "C" void kernel_launch(void* const* d_in, const int* in_sizes, int n_in,
                              void* d_out, int out_size)
{
    const float* inputs = (const float*)d_in[0];
    const float* mask   = (const float*)d_in[1];
    const float* Wq = (const float*)d_in[2];  const float* bq = (const float*)d_in[3];
    const float* Wk = (const float*)d_in[4];  const float* bk = (const float*)d_in[5];
    const float* Wv = (const float*)d_in[6];  const float* bv = (const float*)d_in[7];
    const float* Wo = (const float*)d_in[8];  const float* bo = (const float*)d_in[9];
    const float* ln_g = (const float*)d_in[10];
    const float* ln_b = (const float*)d_in[11];
    float* out = (float*)d_out;

    dim3 gq(DD / Bb_N, MM / Bb_M, 3);
    qkv_gemm_kernel<<<gq, 256>>>(inputs, Wq, bq, Wk, bk, Wv, bv);

    int smem_attn = (4 * 64 * APAD + 64) * (int)sizeof(float);
    cudaFuncSetAttribute(attn_kernel, cudaFuncAttributeMaxDynamicSharedMemorySize, smem_attn);
    attn_kernel<<<dim3(SS / 64, BB * HH), 256, smem_attn>>>(mask);

    ln_kernel<<<MM, 256>>>(inputs, ln_g, ln_b);

    out_gemm_kernel<<<dim3(DD / Bb_N, MM / Bb_M), 256>>>(Wo, bo, mask, out);
}